// round 1
// baseline (speedup 1.0000x reference)
#include <cuda_runtime.h>
#include <cstdint>

// ---------------- problem constants ----------------
#define MAXN    100000
#define NFEAT   512
#define HID     64
#define NCLASS  64
#define ALPHA   0.1f
#define NITER   10

// ---------------- static device scratch (no allocations allowed) ----------------
__device__ float g_h [MAXN * HID];      // relu(x@W1)
__device__ float g_z0[MAXN * NCLASS];   // h@W2
__device__ float g_za[MAXN * NCLASS];   // ping
__device__ float g_zb[MAXN * NCLASS];   // pong

// =================================================================
// GEMM1: C[n,64] = relu(A[n,512] @ B[512,64])
// BM=128, BN=64, BK=32, 256 threads (16x16), TM=8, TN=4
// =================================================================
__global__ __launch_bounds__(256) void gemm1_relu(
    const float* __restrict__ A, const float* __restrict__ B,
    float* __restrict__ C, int n)
{
    __shared__ float As[32][129];   // [k][m], padded
    __shared__ float Bs[32][64];    // [k][n]

    const int tid = threadIdx.x;
    const int tx  = tid & 15;       // 0..15 -> col group
    const int ty  = tid >> 4;       // 0..15 -> row group
    const int bm  = blockIdx.x * 128;

    float acc[8][4];
#pragma unroll
    for (int i = 0; i < 8; i++)
#pragma unroll
        for (int j = 0; j < 4; j++) acc[i][j] = 0.0f;

    for (int kt = 0; kt < NFEAT; kt += 32) {
        // load A tile: 128 rows x 32 k  (1024 float4, 4 per thread)
#pragma unroll
        for (int it = 0; it < 4; it++) {
            int idx = it * 256 + tid;
            int r   = idx >> 3;       // 0..127
            int c4  = idx & 7;        // 0..7
            int row = bm + r;
            float4 v = make_float4(0.f, 0.f, 0.f, 0.f);
            if (row < n)
                v = *reinterpret_cast<const float4*>(A + (size_t)row * NFEAT + kt + c4 * 4);
            As[c4 * 4 + 0][r] = v.x;
            As[c4 * 4 + 1][r] = v.y;
            As[c4 * 4 + 2][r] = v.z;
            As[c4 * 4 + 3][r] = v.w;
        }
        // load B tile: 32 k x 64 n (512 float4, 2 per thread)
#pragma unroll
        for (int it = 0; it < 2; it++) {
            int idx = it * 256 + tid;
            int kr  = idx >> 4;       // 0..31
            int c4  = idx & 15;       // 0..15
            float4 v = *reinterpret_cast<const float4*>(B + (size_t)(kt + kr) * HID + c4 * 4);
            *reinterpret_cast<float4*>(&Bs[kr][c4 * 4]) = v;
        }
        __syncthreads();

#pragma unroll
        for (int k = 0; k < 32; k++) {
            float a[8];
#pragma unroll
            for (int i = 0; i < 8; i++) a[i] = As[k][ty * 8 + i];
            float4 b = *reinterpret_cast<const float4*>(&Bs[k][tx * 4]);
#pragma unroll
            for (int i = 0; i < 8; i++) {
                acc[i][0] = fmaf(a[i], b.x, acc[i][0]);
                acc[i][1] = fmaf(a[i], b.y, acc[i][1]);
                acc[i][2] = fmaf(a[i], b.z, acc[i][2]);
                acc[i][3] = fmaf(a[i], b.w, acc[i][3]);
            }
        }
        __syncthreads();
    }

#pragma unroll
    for (int i = 0; i < 8; i++) {
        int row = bm + ty * 8 + i;
        if (row < n) {
            float4 v;
            v.x = fmaxf(acc[i][0], 0.f);
            v.y = fmaxf(acc[i][1], 0.f);
            v.z = fmaxf(acc[i][2], 0.f);
            v.w = fmaxf(acc[i][3], 0.f);
            *reinterpret_cast<float4*>(C + (size_t)row * HID + tx * 4) = v;
        }
    }
}

// =================================================================
// GEMM2: C[n,64] = A[n,64] @ B[64,64]
// BM=64, BK=64 (single k-tile), 256 threads (16x16), TM=4, TN=4
// =================================================================
__global__ __launch_bounds__(256) void gemm2(
    const float* __restrict__ A, const float* __restrict__ B,
    float* __restrict__ C, int n)
{
    __shared__ float Hs[64][65];    // [k][m], padded
    __shared__ float Ws[64][64];    // [k][n]

    const int tid = threadIdx.x;
    const int tx  = tid & 15;
    const int ty  = tid >> 4;
    const int bm  = blockIdx.x * 64;

    // load A tile 64 rows x 64 k transposed
#pragma unroll
    for (int it = 0; it < 4; it++) {
        int idx = it * 256 + tid;
        int r   = idx >> 4;       // 0..63
        int c4  = idx & 15;       // 0..15
        int row = bm + r;
        float4 v = make_float4(0.f, 0.f, 0.f, 0.f);
        if (row < n)
            v = *reinterpret_cast<const float4*>(A + (size_t)row * HID + c4 * 4);
        Hs[c4 * 4 + 0][r] = v.x;
        Hs[c4 * 4 + 1][r] = v.y;
        Hs[c4 * 4 + 2][r] = v.z;
        Hs[c4 * 4 + 3][r] = v.w;
    }
    // load W2 64x64
#pragma unroll
    for (int it = 0; it < 4; it++) {
        int idx = it * 256 + tid;
        int kr  = idx >> 4;
        int c4  = idx & 15;
        float4 v = *reinterpret_cast<const float4*>(B + (size_t)kr * NCLASS + c4 * 4);
        *reinterpret_cast<float4*>(&Ws[kr][c4 * 4]) = v;
    }
    __syncthreads();

    float acc[4][4];
#pragma unroll
    for (int i = 0; i < 4; i++)
#pragma unroll
        for (int j = 0; j < 4; j++) acc[i][j] = 0.0f;

#pragma unroll
    for (int k = 0; k < 64; k++) {
        float a[4];
#pragma unroll
        for (int i = 0; i < 4; i++) a[i] = Hs[k][ty * 4 + i];
        float4 b = *reinterpret_cast<const float4*>(&Ws[k][tx * 4]);
#pragma unroll
        for (int i = 0; i < 4; i++) {
            acc[i][0] = fmaf(a[i], b.x, acc[i][0]);
            acc[i][1] = fmaf(a[i], b.y, acc[i][1]);
            acc[i][2] = fmaf(a[i], b.z, acc[i][2]);
            acc[i][3] = fmaf(a[i], b.w, acc[i][3]);
        }
    }

#pragma unroll
    for (int i = 0; i < 4; i++) {
        int row = bm + ty * 4 + i;
        if (row < n) {
            float4 v = make_float4(acc[i][0], acc[i][1], acc[i][2], acc[i][3]);
            *reinterpret_cast<float4*>(C + (size_t)row * NCLASS + tx * 4) = v;
        }
    }
}

// =================================================================
// init: zout = ALPHA * z0   (float4 elements)
// =================================================================
__global__ __launch_bounds__(256) void init_z(
    const float* __restrict__ z0, float* __restrict__ zout, int total4)
{
    int i = blockIdx.x * 256 + threadIdx.x;
    if (i < total4) {
        float4 v = reinterpret_cast<const float4*>(z0)[i];
        v.x *= ALPHA; v.y *= ALPHA; v.z *= ALPHA; v.w *= ALPHA;
        reinterpret_cast<float4*>(zout)[i] = v;
    }
}

// =================================================================
// scatter: for each edge e, zout[dst[e]] += ew[e] * zin[src[e]]
// 16 threads per edge, each handles one float4 (4 classes).
// Vector atomics: red.global.add.v4.f32 (sm_90+).
// =================================================================
__global__ __launch_bounds__(256) void scatter_edges(
    const int*   __restrict__ src,
    const int*   __restrict__ dst,
    const float* __restrict__ ew,
    const float* __restrict__ zin,
    float*       __restrict__ zout,
    int e_count)
{
    int gid = blockIdx.x * 256 + threadIdx.x;
    int e   = gid >> 4;
    int c4  = gid & 15;
    if (e >= e_count) return;

    int   s = src[e];
    int   d = dst[e];
    float w = ew[e];

    float4 v = reinterpret_cast<const float4*>(zin + (size_t)s * NCLASS)[c4];
    v.x *= w; v.y *= w; v.z *= w; v.w *= w;

    float* addr = zout + (size_t)d * NCLASS + c4 * 4;
    asm volatile("red.global.add.v4.f32 [%0], {%1, %2, %3, %4};"
                 :: "l"(addr), "f"(v.x), "f"(v.y), "f"(v.z), "f"(v.w)
                 : "memory");
}

// =================================================================
// log_softmax: one warp per node (64 classes, 2 per lane)
// =================================================================
__global__ __launch_bounds__(256) void log_softmax(
    const float* __restrict__ z, float* __restrict__ out, int n)
{
    int node = blockIdx.x * 8 + threadIdx.y;
    if (node >= n) return;
    int lane = threadIdx.x;

    float v0 = z[(size_t)node * NCLASS + lane];
    float v1 = z[(size_t)node * NCLASS + lane + 32];

    float m = fmaxf(v0, v1);
#pragma unroll
    for (int o = 16; o > 0; o >>= 1)
        m = fmaxf(m, __shfl_xor_sync(0xFFFFFFFFu, m, o));

    float s = __expf(v0 - m) + __expf(v1 - m);
#pragma unroll
    for (int o = 16; o > 0; o >>= 1)
        s += __shfl_xor_sync(0xFFFFFFFFu, s, o);

    float l = m + __logf(s);
    out[(size_t)node * NCLASS + lane]      = v0 - l;
    out[(size_t)node * NCLASS + lane + 32] = v1 - l;
}

// =================================================================
// launch
// =================================================================
extern "C" void kernel_launch(void* const* d_in, const int* in_sizes, int n_in,
                              void* d_out, int out_size)
{
    const float* x   = (const float*)d_in[0];   // [N, 512]
    const int*   ei  = (const int*)  d_in[1];   // [2, E]
    const float* ew  = (const float*)d_in[2];   // [E]
    const float* W1  = (const float*)d_in[3];   // [512, 64]
    const float* W2  = (const float*)d_in[4];   // [64, 64]
    float*       out = (float*)d_out;

    const int n = in_sizes[0] / NFEAT;
    const int e = in_sizes[2];
    const int* src = ei;
    const int* dst = ei + e;

    float* h  = nullptr; cudaGetSymbolAddress((void**)&h,  g_h);
    float* z0 = nullptr; cudaGetSymbolAddress((void**)&z0, g_z0);
    float* za = nullptr; cudaGetSymbolAddress((void**)&za, g_za);
    float* zb = nullptr; cudaGetSymbolAddress((void**)&zb, g_zb);

    // feature transform
    gemm1_relu<<<(n + 127) / 128, 256>>>(x, W1, h, n);
    gemm2<<<(n + 63) / 64, 256>>>(h, W2, z0, n);

    // APPNP power iteration
    const int total4 = n * NCLASS / 4;
    const float* zin = z0;
    for (int it = 0; it < NITER; it++) {
        float* zout = (it & 1) ? zb : za;
        init_z<<<(total4 + 255) / 256, 256>>>(z0, zout, total4);
        long long threads = (long long)e * 16;
        scatter_edges<<<(int)((threads + 255) / 256), 256>>>(src, dst, ew, zin, zout, e);
        zin = zout;
    }

    // output
    dim3 blk(32, 8);
    log_softmax<<<(n + 7) / 8, blk>>>(zin, out, n);
}

// round 2
// speedup vs baseline: 2.1236x; 2.1236x over previous
#include <cuda_runtime.h>
#include <cstdint>

// ---------------- problem constants ----------------
#define MAXN    100000
#define MAXE    3200000
#define NFEAT   512
#define HID     64
#define NCLASS  64
#define ALPHA   0.1f
#define NITER   10
#define SCAN_BLK 1024

// ---------------- static device scratch (no allocations allowed) ----------------
__device__ float g_h [MAXN * HID];      // relu(x@W1)
__device__ float g_z0[MAXN * NCLASS];   // h@W2
__device__ float g_za[MAXN * NCLASS];   // ping
__device__ float g_zb[MAXN * NCLASS];   // pong
__device__ int   g_rowptr[MAXN + 1];    // CSR row pointers (by dst)
__device__ int   g_cursor[MAXN];        // histogram / scatter cursors
__device__ int   g_bsums[128];          // scan block sums
__device__ int2  g_edges[MAXE];         // packed {src, weight-bits}, sorted by dst

// =================================================================
// GEMM1: C[n,64] = relu(A[n,512] @ B[512,64])
// =================================================================
__global__ __launch_bounds__(256) void gemm1_relu(
    const float* __restrict__ A, const float* __restrict__ B,
    float* __restrict__ C, int n)
{
    __shared__ float As[32][129];
    __shared__ float Bs[32][64];

    const int tid = threadIdx.x;
    const int tx  = tid & 15;
    const int ty  = tid >> 4;
    const int bm  = blockIdx.x * 128;

    float acc[8][4];
#pragma unroll
    for (int i = 0; i < 8; i++)
#pragma unroll
        for (int j = 0; j < 4; j++) acc[i][j] = 0.0f;

    for (int kt = 0; kt < NFEAT; kt += 32) {
#pragma unroll
        for (int it = 0; it < 4; it++) {
            int idx = it * 256 + tid;
            int r   = idx >> 3;
            int c4  = idx & 7;
            int row = bm + r;
            float4 v = make_float4(0.f, 0.f, 0.f, 0.f);
            if (row < n)
                v = *reinterpret_cast<const float4*>(A + (size_t)row * NFEAT + kt + c4 * 4);
            As[c4 * 4 + 0][r] = v.x;
            As[c4 * 4 + 1][r] = v.y;
            As[c4 * 4 + 2][r] = v.z;
            As[c4 * 4 + 3][r] = v.w;
        }
#pragma unroll
        for (int it = 0; it < 2; it++) {
            int idx = it * 256 + tid;
            int kr  = idx >> 4;
            int c4  = idx & 15;
            float4 v = *reinterpret_cast<const float4*>(B + (size_t)(kt + kr) * HID + c4 * 4);
            *reinterpret_cast<float4*>(&Bs[kr][c4 * 4]) = v;
        }
        __syncthreads();

#pragma unroll
        for (int k = 0; k < 32; k++) {
            float a[8];
#pragma unroll
            for (int i = 0; i < 8; i++) a[i] = As[k][ty * 8 + i];
            float4 b = *reinterpret_cast<const float4*>(&Bs[k][tx * 4]);
#pragma unroll
            for (int i = 0; i < 8; i++) {
                acc[i][0] = fmaf(a[i], b.x, acc[i][0]);
                acc[i][1] = fmaf(a[i], b.y, acc[i][1]);
                acc[i][2] = fmaf(a[i], b.z, acc[i][2]);
                acc[i][3] = fmaf(a[i], b.w, acc[i][3]);
            }
        }
        __syncthreads();
    }

#pragma unroll
    for (int i = 0; i < 8; i++) {
        int row = bm + ty * 8 + i;
        if (row < n) {
            float4 v;
            v.x = fmaxf(acc[i][0], 0.f);
            v.y = fmaxf(acc[i][1], 0.f);
            v.z = fmaxf(acc[i][2], 0.f);
            v.w = fmaxf(acc[i][3], 0.f);
            *reinterpret_cast<float4*>(C + (size_t)row * HID + tx * 4) = v;
        }
    }
}

// =================================================================
// GEMM2: C[n,64] = A[n,64] @ B[64,64]
// =================================================================
__global__ __launch_bounds__(256) void gemm2(
    const float* __restrict__ A, const float* __restrict__ B,
    float* __restrict__ C, int n)
{
    __shared__ float Hs[64][65];
    __shared__ float Ws[64][64];

    const int tid = threadIdx.x;
    const int tx  = tid & 15;
    const int ty  = tid >> 4;
    const int bm  = blockIdx.x * 64;

#pragma unroll
    for (int it = 0; it < 4; it++) {
        int idx = it * 256 + tid;
        int r   = idx >> 4;
        int c4  = idx & 15;
        int row = bm + r;
        float4 v = make_float4(0.f, 0.f, 0.f, 0.f);
        if (row < n)
            v = *reinterpret_cast<const float4*>(A + (size_t)row * HID + c4 * 4);
        Hs[c4 * 4 + 0][r] = v.x;
        Hs[c4 * 4 + 1][r] = v.y;
        Hs[c4 * 4 + 2][r] = v.z;
        Hs[c4 * 4 + 3][r] = v.w;
    }
#pragma unroll
    for (int it = 0; it < 4; it++) {
        int idx = it * 256 + tid;
        int kr  = idx >> 4;
        int c4  = idx & 15;
        float4 v = *reinterpret_cast<const float4*>(B + (size_t)kr * NCLASS + c4 * 4);
        *reinterpret_cast<float4*>(&Ws[kr][c4 * 4]) = v;
    }
    __syncthreads();

    float acc[4][4];
#pragma unroll
    for (int i = 0; i < 4; i++)
#pragma unroll
        for (int j = 0; j < 4; j++) acc[i][j] = 0.0f;

#pragma unroll
    for (int k = 0; k < 64; k++) {
        float a[4];
#pragma unroll
        for (int i = 0; i < 4; i++) a[i] = Hs[k][ty * 4 + i];
        float4 b = *reinterpret_cast<const float4*>(&Ws[k][tx * 4]);
#pragma unroll
        for (int i = 0; i < 4; i++) {
            acc[i][0] = fmaf(a[i], b.x, acc[i][0]);
            acc[i][1] = fmaf(a[i], b.y, acc[i][1]);
            acc[i][2] = fmaf(a[i], b.z, acc[i][2]);
            acc[i][3] = fmaf(a[i], b.w, acc[i][3]);
        }
    }

#pragma unroll
    for (int i = 0; i < 4; i++) {
        int row = bm + ty * 4 + i;
        if (row < n) {
            float4 v = make_float4(acc[i][0], acc[i][1], acc[i][2], acc[i][3]);
            *reinterpret_cast<float4*>(C + (size_t)row * NCLASS + tx * 4) = v;
        }
    }
}

// =================================================================
// CSR construction: zero -> histogram -> scan(3) -> build
// =================================================================
__global__ __launch_bounds__(256) void zero_hist(int* __restrict__ cnt, int n)
{
    int i = blockIdx.x * 256 + threadIdx.x;
    if (i < n) cnt[i] = 0;
}

__global__ __launch_bounds__(256) void hist_dst(
    const int* __restrict__ dst, int* __restrict__ cnt, int e)
{
    int i = blockIdx.x * 256 + threadIdx.x;
    if (i < e) atomicAdd(&cnt[dst[i]], 1);
}

// block-local exclusive scan of cnt -> rowptr (pre-offset), block totals -> bsums
__global__ __launch_bounds__(SCAN_BLK) void scan1(
    const int* __restrict__ cnt, int* __restrict__ rowptr,
    int* __restrict__ bsums, int n)
{
    __shared__ int sh[SCAN_BLK];
    int t = threadIdx.x;
    int i = blockIdx.x * SCAN_BLK + t;
    int v = (i < n) ? cnt[i] : 0;
    sh[t] = v;
    __syncthreads();
#pragma unroll
    for (int off = 1; off < SCAN_BLK; off <<= 1) {
        int x = (t >= off) ? sh[t - off] : 0;
        __syncthreads();
        sh[t] += x;
        __syncthreads();
    }
    int incl = sh[t];
    if (i < n) rowptr[i] = incl - v;          // exclusive, block-local
    if (t == SCAN_BLK - 1) bsums[blockIdx.x] = incl;
}

// single-block exclusive scan of block sums (nb <= 128)
__global__ __launch_bounds__(128) void scan2(int* __restrict__ bsums, int nb)
{
    __shared__ int sh[128];
    int t = threadIdx.x;
    int v = (t < nb) ? bsums[t] : 0;
    sh[t] = v;
    __syncthreads();
#pragma unroll
    for (int off = 1; off < 128; off <<= 1) {
        int x = (t >= off) ? sh[t - off] : 0;
        __syncthreads();
        sh[t] += x;
        __syncthreads();
    }
    if (t < nb) bsums[t] = sh[t] - v;          // exclusive
}

// add block offsets; duplicate into cursor; set rowptr[n] = e
__global__ __launch_bounds__(256) void scan3(
    int* __restrict__ rowptr, int* __restrict__ cursor,
    const int* __restrict__ bsums, int n, int e)
{
    int i = blockIdx.x * 256 + threadIdx.x;
    if (i < n) {
        int v = rowptr[i] + bsums[i >> 10];
        rowptr[i] = v;
        cursor[i] = v;
    }
    if (i == n) rowptr[n] = e;
}

__global__ __launch_bounds__(256) void build_edges(
    const int* __restrict__ src, const int* __restrict__ dst,
    const float* __restrict__ ew, int* __restrict__ cursor,
    int2* __restrict__ edges, int e)
{
    int i = blockIdx.x * 256 + threadIdx.x;
    if (i < e) {
        int d = dst[i];
        int pos = atomicAdd(&cursor[d], 1);
        edges[pos] = make_int2(src[i], __float_as_int(ew[i]));
    }
}

// =================================================================
// gather: one warp per dst node.
//   zout[d] = sum_{e in in(d)} w_e * zin[src_e] + ALPHA * z0[d]
// Half-warp per edge: lanes split into 2 halves of 16; each half
// processes alternate edges with LDG.128 row loads (16 x float4 = 256B).
// LAST: fuse log_softmax and write to out.
// =================================================================
template<bool LAST>
__global__ __launch_bounds__(256) void gather_nodes(
    const int2* __restrict__ edges, const int* __restrict__ rowptr,
    const float* __restrict__ zin, const float* __restrict__ z0,
    float* __restrict__ zout, int n)
{
    int warp = (blockIdx.x * 256 + threadIdx.x) >> 5;
    if (warp >= n) return;
    int lane = threadIdx.x & 31;
    int half = lane >> 4;        // 0 or 1
    int c4   = lane & 15;        // float4 index within row

    int beg = __ldg(&rowptr[warp]);
    int end = __ldg(&rowptr[warp + 1]);

    float4 acc = make_float4(0.f, 0.f, 0.f, 0.f);

    int i = beg + half;
    // unrolled-by-2 (per half) main loop for MLP
    for (; i + 2 < end; i += 4) {
        int2 e0 = __ldg(&edges[i]);
        int2 e1 = __ldg(&edges[i + 2]);
        float w0 = __int_as_float(e0.y);
        float w1 = __int_as_float(e1.y);
        float4 v0 = __ldg(reinterpret_cast<const float4*>(zin + (size_t)e0.x * NCLASS) + c4);
        float4 v1 = __ldg(reinterpret_cast<const float4*>(zin + (size_t)e1.x * NCLASS) + c4);
        acc.x = fmaf(w0, v0.x, acc.x);
        acc.y = fmaf(w0, v0.y, acc.y);
        acc.z = fmaf(w0, v0.z, acc.z);
        acc.w = fmaf(w0, v0.w, acc.w);
        acc.x = fmaf(w1, v1.x, acc.x);
        acc.y = fmaf(w1, v1.y, acc.y);
        acc.z = fmaf(w1, v1.z, acc.z);
        acc.w = fmaf(w1, v1.w, acc.w);
    }
    for (; i < end; i += 2) {
        int2 e0 = __ldg(&edges[i]);
        float w0 = __int_as_float(e0.y);
        float4 v0 = __ldg(reinterpret_cast<const float4*>(zin + (size_t)e0.x * NCLASS) + c4);
        acc.x = fmaf(w0, v0.x, acc.x);
        acc.y = fmaf(w0, v0.y, acc.y);
        acc.z = fmaf(w0, v0.z, acc.z);
        acc.w = fmaf(w0, v0.w, acc.w);
    }

    // combine the two halves (both halves end with identical totals)
    const unsigned FULL = 0xFFFFFFFFu;
    acc.x += __shfl_xor_sync(FULL, acc.x, 16);
    acc.y += __shfl_xor_sync(FULL, acc.y, 16);
    acc.z += __shfl_xor_sync(FULL, acc.z, 16);
    acc.w += __shfl_xor_sync(FULL, acc.w, 16);

    // + alpha * z0
    float4 z0v = __ldg(reinterpret_cast<const float4*>(z0 + (size_t)warp * NCLASS) + c4);
    acc.x = fmaf(ALPHA, z0v.x, acc.x);
    acc.y = fmaf(ALPHA, z0v.y, acc.y);
    acc.z = fmaf(ALPHA, z0v.z, acc.z);
    acc.w = fmaf(ALPHA, z0v.w, acc.w);

    if (!LAST) {
        if (half == 0)
            reinterpret_cast<float4*>(zout + (size_t)warp * NCLASS)[c4] = acc;
    } else {
        // log_softmax over the 64 values held across 16 lanes (x2 identical halves)
        float m = fmaxf(fmaxf(acc.x, acc.y), fmaxf(acc.z, acc.w));
#pragma unroll
        for (int o = 8; o > 0; o >>= 1)
            m = fmaxf(m, __shfl_xor_sync(FULL, m, o));
        float s = __expf(acc.x - m) + __expf(acc.y - m) +
                  __expf(acc.z - m) + __expf(acc.w - m);
#pragma unroll
        for (int o = 8; o > 0; o >>= 1)
            s += __shfl_xor_sync(FULL, s, o);
        float l = m + __logf(s);
        if (half == 0) {
            float4 r = make_float4(acc.x - l, acc.y - l, acc.z - l, acc.w - l);
            reinterpret_cast<float4*>(zout + (size_t)warp * NCLASS)[c4] = r;
        }
    }
}

// =================================================================
// launch
// =================================================================
extern "C" void kernel_launch(void* const* d_in, const int* in_sizes, int n_in,
                              void* d_out, int out_size)
{
    const float* x   = (const float*)d_in[0];   // [N, 512]
    const int*   ei  = (const int*)  d_in[1];   // [2, E]
    const float* ew  = (const float*)d_in[2];   // [E]
    const float* W1  = (const float*)d_in[3];   // [512, 64]
    const float* W2  = (const float*)d_in[4];   // [64, 64]
    float*       out = (float*)d_out;

    const int n = in_sizes[0] / NFEAT;
    const int e = in_sizes[2];
    const int* src = ei;
    const int* dst = ei + e;

    float* h   = nullptr; cudaGetSymbolAddress((void**)&h,   g_h);
    float* z0  = nullptr; cudaGetSymbolAddress((void**)&z0,  g_z0);
    float* za  = nullptr; cudaGetSymbolAddress((void**)&za,  g_za);
    float* zb  = nullptr; cudaGetSymbolAddress((void**)&zb,  g_zb);
    int*   rp  = nullptr; cudaGetSymbolAddress((void**)&rp,  g_rowptr);
    int*   cur = nullptr; cudaGetSymbolAddress((void**)&cur, g_cursor);
    int*   bs  = nullptr; cudaGetSymbolAddress((void**)&bs,  g_bsums);
    int2*  edg = nullptr; cudaGetSymbolAddress((void**)&edg, g_edges);

    // ---- feature transform ----
    gemm1_relu<<<(n + 127) / 128, 256>>>(x, W1, h, n);
    gemm2<<<(n + 63) / 64, 256>>>(h, W2, z0, n);

    // ---- build CSR (by dst) ----
    zero_hist<<<(n + 255) / 256, 256>>>(cur, n);
    hist_dst<<<(e + 255) / 256, 256>>>(dst, cur, e);
    int nb = (n + SCAN_BLK - 1) / SCAN_BLK;
    scan1<<<nb, SCAN_BLK>>>(cur, rp, bs, n);
    scan2<<<1, 128>>>(bs, nb);
    scan3<<<(n + 256) / 256, 256>>>(rp, cur, bs, n, e);
    build_edges<<<(e + 255) / 256, 256>>>(src, dst, ew, cur, edg, e);

    // ---- APPNP power iteration (gather form) ----
    const int gblocks = (n * 32 + 255) / 256;
    const float* zin = z0;
    for (int it = 0; it < NITER - 1; it++) {
        float* zout = (it & 1) ? zb : za;
        gather_nodes<false><<<gblocks, 256>>>(edg, rp, zin, z0, zout, n);
        zin = zout;
    }
    // last iteration: fused log_softmax -> out
    gather_nodes<true><<<gblocks, 256>>>(edg, rp, zin, z0, out, n);
}

// round 3
// speedup vs baseline: 2.1881x; 1.0304x over previous
#include <cuda_runtime.h>
#include <cstdint>

// ---------------- problem constants ----------------
#define MAXN    100000
#define MAXE    3200000
#define NFEAT   512
#define HID     64
#define NCLASS  64
#define ALPHA   0.1f
#define NITER   10
#define SCAN_BLK 1024

// ---------------- static device scratch (no allocations allowed) ----------------
__device__ float g_z0[MAXN * NCLASS];   // relu(x@W1)@W2
__device__ float g_za[MAXN * NCLASS];   // ping
__device__ float g_zb[MAXN * NCLASS];   // pong
__device__ int   g_rowptr[MAXN + 1];    // CSR row pointers (by dst)
__device__ int   g_cursor[MAXN];        // histogram / scatter cursors
__device__ int   g_bsums[128];          // scan block sums
__device__ int2  g_edges[MAXE];         // packed {src, weight-bits}, sorted by dst

// =================================================================
// Fused GEMM: z0[n,64] = relu(x[n,512] @ W1[512,64]) @ W2[64,64]
// BM=128, BN=64, BK=32, 256 threads (16x16), TM=8, TN=4.
// Double-buffered smem for phase 1; phase 2 reuses smem for h and W2.
// =================================================================
#define AS_TILE (32 * 132)     // [k][m] padded (132*4B = 528B rows, 16B aligned)
#define BS_TILE (32 * 64)
#define HS_SIZE (128 * 68)     // [m][k] padded (68*4B = 272B rows, 16B aligned)
#define WS_SIZE (64 * 64)
#define SMEM_FLOATS 12800      // max(2*AS+2*BS=12544, HS+WS=12800)

__global__ __launch_bounds__(256) void gemm_fused(
    const float* __restrict__ A, const float* __restrict__ W1,
    const float* __restrict__ W2, float* __restrict__ C, int n)
{
    extern __shared__ float sm[];
    float* As = sm;                 // [2][AS_TILE]
    float* Bs = sm + 2 * AS_TILE;   // [2][BS_TILE]
    float* Hs = sm;                 // phase 2 (overlays As/Bs)
    float* Ws = sm + HS_SIZE;

    const int tid = threadIdx.x;
    const int tx  = tid & 15;
    const int ty  = tid >> 4;
    const int bm  = blockIdx.x * 128;

    float acc[8][4];
#pragma unroll
    for (int i = 0; i < 8; i++)
#pragma unroll
        for (int j = 0; j < 4; j++) acc[i][j] = 0.0f;

    // ---- load tile 0 ----
    {
#pragma unroll
        for (int it = 0; it < 4; it++) {
            int idx = it * 256 + tid;
            int r   = idx >> 3;
            int c4  = idx & 7;
            int row = bm + r;
            float4 v = make_float4(0.f, 0.f, 0.f, 0.f);
            if (row < n)
                v = *reinterpret_cast<const float4*>(A + (size_t)row * NFEAT + c4 * 4);
            As[(c4 * 4 + 0) * 132 + r] = v.x;
            As[(c4 * 4 + 1) * 132 + r] = v.y;
            As[(c4 * 4 + 2) * 132 + r] = v.z;
            As[(c4 * 4 + 3) * 132 + r] = v.w;
        }
#pragma unroll
        for (int it = 0; it < 2; it++) {
            int idx = it * 256 + tid;
            int kr  = idx >> 4;
            int c4  = idx & 15;
            *reinterpret_cast<float4*>(&Bs[kr * 64 + c4 * 4]) =
                *reinterpret_cast<const float4*>(W1 + (size_t)kr * HID + c4 * 4);
        }
    }
    __syncthreads();

    // ---- 16 k-tiles, double buffered ----
    for (int t = 0; t < 16; t++) {
        float4 pa[4];
        float4 pb[2];
        const bool more = (t < 15);
        if (more) {
            int kt = (t + 1) * 32;
#pragma unroll
            for (int it = 0; it < 4; it++) {
                int idx = it * 256 + tid;
                int r   = idx >> 3;
                int c4  = idx & 7;
                int row = bm + r;
                pa[it] = make_float4(0.f, 0.f, 0.f, 0.f);
                if (row < n)
                    pa[it] = *reinterpret_cast<const float4*>(A + (size_t)row * NFEAT + kt + c4 * 4);
            }
#pragma unroll
            for (int it = 0; it < 2; it++) {
                int idx = it * 256 + tid;
                int kr  = idx >> 4;
                int c4  = idx & 15;
                pb[it] = *reinterpret_cast<const float4*>(W1 + (size_t)(kt + kr) * HID + c4 * 4);
            }
        }

        const float* AsB = As + (t & 1) * AS_TILE;
        const float* BsB = Bs + (t & 1) * BS_TILE;
#pragma unroll
        for (int k = 0; k < 32; k++) {
            float4 a0 = *reinterpret_cast<const float4*>(&AsB[k * 132 + ty * 8]);
            float4 a1 = *reinterpret_cast<const float4*>(&AsB[k * 132 + ty * 8 + 4]);
            float4 b  = *reinterpret_cast<const float4*>(&BsB[k * 64 + tx * 4]);
            acc[0][0] = fmaf(a0.x, b.x, acc[0][0]); acc[0][1] = fmaf(a0.x, b.y, acc[0][1]);
            acc[0][2] = fmaf(a0.x, b.z, acc[0][2]); acc[0][3] = fmaf(a0.x, b.w, acc[0][3]);
            acc[1][0] = fmaf(a0.y, b.x, acc[1][0]); acc[1][1] = fmaf(a0.y, b.y, acc[1][1]);
            acc[1][2] = fmaf(a0.y, b.z, acc[1][2]); acc[1][3] = fmaf(a0.y, b.w, acc[1][3]);
            acc[2][0] = fmaf(a0.z, b.x, acc[2][0]); acc[2][1] = fmaf(a0.z, b.y, acc[2][1]);
            acc[2][2] = fmaf(a0.z, b.z, acc[2][2]); acc[2][3] = fmaf(a0.z, b.w, acc[2][3]);
            acc[3][0] = fmaf(a0.w, b.x, acc[3][0]); acc[3][1] = fmaf(a0.w, b.y, acc[3][1]);
            acc[3][2] = fmaf(a0.w, b.z, acc[3][2]); acc[3][3] = fmaf(a0.w, b.w, acc[3][3]);
            acc[4][0] = fmaf(a1.x, b.x, acc[4][0]); acc[4][1] = fmaf(a1.x, b.y, acc[4][1]);
            acc[4][2] = fmaf(a1.x, b.z, acc[4][2]); acc[4][3] = fmaf(a1.x, b.w, acc[4][3]);
            acc[5][0] = fmaf(a1.y, b.x, acc[5][0]); acc[5][1] = fmaf(a1.y, b.y, acc[5][1]);
            acc[5][2] = fmaf(a1.y, b.z, acc[5][2]); acc[5][3] = fmaf(a1.y, b.w, acc[5][3]);
            acc[6][0] = fmaf(a1.z, b.x, acc[6][0]); acc[6][1] = fmaf(a1.z, b.y, acc[6][1]);
            acc[6][2] = fmaf(a1.z, b.z, acc[6][2]); acc[6][3] = fmaf(a1.z, b.w, acc[6][3]);
            acc[7][0] = fmaf(a1.w, b.x, acc[7][0]); acc[7][1] = fmaf(a1.w, b.y, acc[7][1]);
            acc[7][2] = fmaf(a1.w, b.z, acc[7][2]); acc[7][3] = fmaf(a1.w, b.w, acc[7][3]);
        }

        if (more) {
            float* AsN = As + ((t + 1) & 1) * AS_TILE;
            float* BsN = Bs + ((t + 1) & 1) * BS_TILE;
#pragma unroll
            for (int it = 0; it < 4; it++) {
                int idx = it * 256 + tid;
                int r   = idx >> 3;
                int c4  = idx & 7;
                AsN[(c4 * 4 + 0) * 132 + r] = pa[it].x;
                AsN[(c4 * 4 + 1) * 132 + r] = pa[it].y;
                AsN[(c4 * 4 + 2) * 132 + r] = pa[it].z;
                AsN[(c4 * 4 + 3) * 132 + r] = pa[it].w;
            }
#pragma unroll
            for (int it = 0; it < 2; it++) {
                int idx = it * 256 + tid;
                int kr  = idx >> 4;
                int c4  = idx & 15;
                *reinterpret_cast<float4*>(&BsN[kr * 64 + c4 * 4]) = pb[it];
            }
            __syncthreads();
        }
    }

    // ---- phase 2: z0 = relu(h) @ W2 ----
    __syncthreads();   // everyone done reading As/Bs before overlay

    // relu(h) -> Hs[m][k] (float4 rows, 272B stride)
#pragma unroll
    for (int i = 0; i < 8; i++) {
        float4 v;
        v.x = fmaxf(acc[i][0], 0.f);
        v.y = fmaxf(acc[i][1], 0.f);
        v.z = fmaxf(acc[i][2], 0.f);
        v.w = fmaxf(acc[i][3], 0.f);
        *reinterpret_cast<float4*>(&Hs[(ty * 8 + i) * 68 + tx * 4]) = v;
    }
    // W2 -> Ws
#pragma unroll
    for (int it = 0; it < 4; it++) {
        int idx = it * 256 + tid;
        int kr  = idx >> 4;
        int c4  = idx & 15;
        *reinterpret_cast<float4*>(&Ws[kr * 64 + c4 * 4]) =
            *reinterpret_cast<const float4*>(W2 + (size_t)kr * NCLASS + c4 * 4);
    }
    __syncthreads();

    float acc2[8][4];
#pragma unroll
    for (int i = 0; i < 8; i++)
#pragma unroll
        for (int j = 0; j < 4; j++) acc2[i][j] = 0.0f;

#pragma unroll
    for (int k = 0; k < 64; k++) {
        float4 b = *reinterpret_cast<const float4*>(&Ws[k * 64 + tx * 4]);
#pragma unroll
        for (int i = 0; i < 8; i++) {
            float a = Hs[(ty * 8 + i) * 68 + k];
            acc2[i][0] = fmaf(a, b.x, acc2[i][0]);
            acc2[i][1] = fmaf(a, b.y, acc2[i][1]);
            acc2[i][2] = fmaf(a, b.z, acc2[i][2]);
            acc2[i][3] = fmaf(a, b.w, acc2[i][3]);
        }
    }

#pragma unroll
    for (int i = 0; i < 8; i++) {
        int row = bm + ty * 8 + i;
        if (row < n) {
            float4 v = make_float4(acc2[i][0], acc2[i][1], acc2[i][2], acc2[i][3]);
            *reinterpret_cast<float4*>(C + (size_t)row * NCLASS + tx * 4) = v;
        }
    }
}

// =================================================================
// CSR construction: zero -> histogram -> scan(3) -> build
// =================================================================
__global__ __launch_bounds__(256) void zero_hist(int* __restrict__ cnt, int n)
{
    int i = blockIdx.x * 256 + threadIdx.x;
    if (i < n) cnt[i] = 0;
}

__global__ __launch_bounds__(256) void hist_dst(
    const int* __restrict__ dst, int* __restrict__ cnt, int e)
{
    int i = blockIdx.x * 256 + threadIdx.x;
    if (i < e) atomicAdd(&cnt[dst[i]], 1);
}

__global__ __launch_bounds__(SCAN_BLK) void scan1(
    const int* __restrict__ cnt, int* __restrict__ rowptr,
    int* __restrict__ bsums, int n)
{
    __shared__ int sh[SCAN_BLK];
    int t = threadIdx.x;
    int i = blockIdx.x * SCAN_BLK + t;
    int v = (i < n) ? cnt[i] : 0;
    sh[t] = v;
    __syncthreads();
#pragma unroll
    for (int off = 1; off < SCAN_BLK; off <<= 1) {
        int x = (t >= off) ? sh[t - off] : 0;
        __syncthreads();
        sh[t] += x;
        __syncthreads();
    }
    int incl = sh[t];
    if (i < n) rowptr[i] = incl - v;
    if (t == SCAN_BLK - 1) bsums[blockIdx.x] = incl;
}

__global__ __launch_bounds__(128) void scan2(int* __restrict__ bsums, int nb)
{
    __shared__ int sh[128];
    int t = threadIdx.x;
    int v = (t < nb) ? bsums[t] : 0;
    sh[t] = v;
    __syncthreads();
#pragma unroll
    for (int off = 1; off < 128; off <<= 1) {
        int x = (t >= off) ? sh[t - off] : 0;
        __syncthreads();
        sh[t] += x;
        __syncthreads();
    }
    if (t < nb) bsums[t] = sh[t] - v;
}

__global__ __launch_bounds__(256) void scan3(
    int* __restrict__ rowptr, int* __restrict__ cursor,
    const int* __restrict__ bsums, int n, int e)
{
    int i = blockIdx.x * 256 + threadIdx.x;
    if (i < n) {
        int v = rowptr[i] + bsums[i >> 10];
        rowptr[i] = v;
        cursor[i] = v;
    }
    if (i == n) rowptr[n] = e;
}

__global__ __launch_bounds__(256) void build_edges(
    const int* __restrict__ src, const int* __restrict__ dst,
    const float* __restrict__ ew, int* __restrict__ cursor,
    int2* __restrict__ edges, int e)
{
    int i = blockIdx.x * 256 + threadIdx.x;
    if (i < e) {
        int d = dst[i];
        int pos = atomicAdd(&cursor[d], 1);
        edges[pos] = make_int2(src[i], __float_as_int(ew[i]));
    }
}

// =================================================================
// gather: one warp per dst node; half-warp per edge.
// =================================================================
template<bool LAST>
__global__ __launch_bounds__(256) void gather_nodes(
    const int2* __restrict__ edges, const int* __restrict__ rowptr,
    const float* __restrict__ zin, const float* __restrict__ z0,
    float* __restrict__ zout, int n)
{
    int warp = (blockIdx.x * 256 + threadIdx.x) >> 5;
    if (warp >= n) return;
    int lane = threadIdx.x & 31;
    int half = lane >> 4;
    int c4   = lane & 15;

    int beg = __ldg(&rowptr[warp]);
    int end = __ldg(&rowptr[warp + 1]);

    float4 acc = make_float4(0.f, 0.f, 0.f, 0.f);

    int i = beg + half;
    for (; i + 2 < end; i += 4) {
        int2 e0 = __ldg(&edges[i]);
        int2 e1 = __ldg(&edges[i + 2]);
        float w0 = __int_as_float(e0.y);
        float w1 = __int_as_float(e1.y);
        float4 v0 = __ldg(reinterpret_cast<const float4*>(zin + (size_t)e0.x * NCLASS) + c4);
        float4 v1 = __ldg(reinterpret_cast<const float4*>(zin + (size_t)e1.x * NCLASS) + c4);
        acc.x = fmaf(w0, v0.x, acc.x);
        acc.y = fmaf(w0, v0.y, acc.y);
        acc.z = fmaf(w0, v0.z, acc.z);
        acc.w = fmaf(w0, v0.w, acc.w);
        acc.x = fmaf(w1, v1.x, acc.x);
        acc.y = fmaf(w1, v1.y, acc.y);
        acc.z = fmaf(w1, v1.z, acc.z);
        acc.w = fmaf(w1, v1.w, acc.w);
    }
    for (; i < end; i += 2) {
        int2 e0 = __ldg(&edges[i]);
        float w0 = __int_as_float(e0.y);
        float4 v0 = __ldg(reinterpret_cast<const float4*>(zin + (size_t)e0.x * NCLASS) + c4);
        acc.x = fmaf(w0, v0.x, acc.x);
        acc.y = fmaf(w0, v0.y, acc.y);
        acc.z = fmaf(w0, v0.z, acc.z);
        acc.w = fmaf(w0, v0.w, acc.w);
    }

    const unsigned FULL = 0xFFFFFFFFu;
    acc.x += __shfl_xor_sync(FULL, acc.x, 16);
    acc.y += __shfl_xor_sync(FULL, acc.y, 16);
    acc.z += __shfl_xor_sync(FULL, acc.z, 16);
    acc.w += __shfl_xor_sync(FULL, acc.w, 16);

    float4 z0v = __ldg(reinterpret_cast<const float4*>(z0 + (size_t)warp * NCLASS) + c4);
    acc.x = fmaf(ALPHA, z0v.x, acc.x);
    acc.y = fmaf(ALPHA, z0v.y, acc.y);
    acc.z = fmaf(ALPHA, z0v.z, acc.z);
    acc.w = fmaf(ALPHA, z0v.w, acc.w);

    if (!LAST) {
        if (half == 0)
            reinterpret_cast<float4*>(zout + (size_t)warp * NCLASS)[c4] = acc;
    } else {
        float m = fmaxf(fmaxf(acc.x, acc.y), fmaxf(acc.z, acc.w));
#pragma unroll
        for (int o = 8; o > 0; o >>= 1)
            m = fmaxf(m, __shfl_xor_sync(FULL, m, o));
        float s = __expf(acc.x - m) + __expf(acc.y - m) +
                  __expf(acc.z - m) + __expf(acc.w - m);
#pragma unroll
        for (int o = 8; o > 0; o >>= 1)
            s += __shfl_xor_sync(FULL, s, o);
        float l = m + __logf(s);
        if (half == 0) {
            float4 r = make_float4(acc.x - l, acc.y - l, acc.z - l, acc.w - l);
            reinterpret_cast<float4*>(zout + (size_t)warp * NCLASS)[c4] = r;
        }
    }
}

// =================================================================
// launch: GEMM chain on side stream, CSR on capture stream, join.
// =================================================================
extern "C" void kernel_launch(void* const* d_in, const int* in_sizes, int n_in,
                              void* d_out, int out_size)
{
    const float* x   = (const float*)d_in[0];   // [N, 512]
    const int*   ei  = (const int*)  d_in[1];   // [2, E]
    const float* ew  = (const float*)d_in[2];   // [E]
    const float* W1  = (const float*)d_in[3];   // [512, 64]
    const float* W2  = (const float*)d_in[4];   // [64, 64]
    float*       out = (float*)d_out;

    const int n = in_sizes[0] / NFEAT;
    const int e = in_sizes[2];
    const int* src = ei;
    const int* dst = ei + e;

    float* z0  = nullptr; cudaGetSymbolAddress((void**)&z0,  g_z0);
    float* za  = nullptr; cudaGetSymbolAddress((void**)&za,  g_za);
    float* zb  = nullptr; cudaGetSymbolAddress((void**)&zb,  g_zb);
    int*   rp  = nullptr; cudaGetSymbolAddress((void**)&rp,  g_rowptr);
    int*   cur = nullptr; cudaGetSymbolAddress((void**)&cur, g_cursor);
    int*   bs  = nullptr; cudaGetSymbolAddress((void**)&bs,  g_bsums);
    int2*  edg = nullptr; cudaGetSymbolAddress((void**)&edg, g_edges);

    static cudaStream_t sG = nullptr;
    static cudaEvent_t  evF = nullptr, evG = nullptr;
    if (sG == nullptr) {
        cudaStreamCreateWithFlags(&sG, cudaStreamNonBlocking);
        cudaEventCreateWithFlags(&evF, cudaEventDisableTiming);
        cudaEventCreateWithFlags(&evG, cudaEventDisableTiming);
        cudaFuncSetAttribute(gemm_fused,
            cudaFuncAttributeMaxDynamicSharedMemorySize, SMEM_FLOATS * 4);
    }

    // ---- fork: GEMM chain on sG ----
    cudaEventRecord(evF, 0);
    cudaStreamWaitEvent(sG, evF, 0);
    gemm_fused<<<(n + 127) / 128, 256, SMEM_FLOATS * 4, sG>>>(x, W1, W2, z0, n);
    cudaEventRecord(evG, sG);

    // ---- CSR build on capture (default) stream ----
    zero_hist<<<(n + 255) / 256, 256>>>(cur, n);
    hist_dst<<<(e + 255) / 256, 256>>>(dst, cur, e);
    int nb = (n + SCAN_BLK - 1) / SCAN_BLK;
    scan1<<<nb, SCAN_BLK>>>(cur, rp, bs, n);
    scan2<<<1, 128>>>(bs, nb);
    scan3<<<(n + 256) / 256, 256>>>(rp, cur, bs, n, e);
    build_edges<<<(e + 255) / 256, 256>>>(src, dst, ew, cur, edg, e);

    // ---- join ----
    cudaStreamWaitEvent(0, evG, 0);

    // ---- APPNP power iteration (gather form) ----
    const int gblocks = (n * 32 + 255) / 256;
    const float* zin = z0;
    for (int it = 0; it < NITER - 1; it++) {
        float* zout = (it & 1) ? zb : za;
        gather_nodes<false><<<gblocks, 256>>>(edg, rp, zin, z0, zout, n);
        zin = zout;
    }
    gather_nodes<true><<<gblocks, 256>>>(edg, rp, zin, z0, out, n);
}